// round 6
// baseline (speedup 1.0000x reference)
#include <cuda_runtime.h>
#include <cuda_bf16.h>
#include <cstdint>

// ---------------- Problem constants ----------------
#define BATCH 16
#define NQ    2048
#define NK    2048
#define DIM   128
#define DVAL  128

// ---------------- Tiling ----------------
#define BM 64
#define BN 32
#define NTHREADS 128   // 4 warps; warp w owns q-rows [w*16, w*16+16)

// ---------------- Precomputed split K/V (device globals; allowed scratch) ----------------
__device__ __nv_bfloat16 gKhi[BATCH * NK * DIM];     // [b][key][d]
__device__ __nv_bfloat16 gKlo[BATCH * NK * DIM];
__device__ __nv_bfloat16 gVThi[BATCH * DVAL * NK];   // [b][dv][key]  (transposed)
__device__ __nv_bfloat16 gVTlo[BATCH * DVAL * NK];

// ---------------- SMEM layout (bytes) ----------------
// Per stage:
//   K tile : 32 keys x 128 d bf16 hi+lo, padded row = 272 B (conflict-free ldmatrix)
//   VT tile: 128 dv x 32 keys bf16 hi+lo, padded row = 80 B
#define KROW 272
#define VROW 80
#define SKHI  0
#define SKLO  8704
#define SVTHI 17408
#define SVTLO 27648
#define STAGE 37888
#define SM_TOTAL (2 * STAGE)       // 75776 B -> 3 CTAs/SM (225KB incl. overhead)

// Q staging area inside stage-1 region (prologue only; tile 1 arrives later)
#define SQH STAGE                  // 27648? no: = 37888
#define SQL (STAGE + 17408)        // 55296 ; ends 72704 <= 75776 ✓

// ---------------- PTX helpers ----------------
__device__ __forceinline__ uint32_t smem_u32(const void* p) {
    uint32_t a;
    asm("{ .reg .u64 t; cvta.to.shared.u64 t, %1; cvt.u32.u64 %0, t; }" : "=r"(a) : "l"(p));
    return a;
}
__device__ __forceinline__ void ldsm4(uint32_t* r, uint32_t addr) {
    asm volatile("ldmatrix.sync.aligned.m8n8.x4.shared.b16 {%0,%1,%2,%3}, [%4];"
                 : "=r"(r[0]), "=r"(r[1]), "=r"(r[2]), "=r"(r[3]) : "r"(addr));
}
__device__ __forceinline__ void mma16816(float* c, const uint32_t* a, uint32_t b0, uint32_t b1) {
    asm volatile("mma.sync.aligned.m16n8k16.row.col.f32.bf16.bf16.f32 "
                 "{%0,%1,%2,%3}, {%4,%5,%6,%7}, {%8,%9}, {%0,%1,%2,%3};"
                 : "+f"(c[0]), "+f"(c[1]), "+f"(c[2]), "+f"(c[3])
                 : "r"(a[0]), "r"(a[1]), "r"(a[2]), "r"(a[3]), "r"(b0), "r"(b1));
}
#define CPA16(dst, src) \
    asm volatile("cp.async.cg.shared.global [%0], [%1], 16;" :: "r"(dst), "l"(src))
#define CPA_COMMIT() asm volatile("cp.async.commit_group;" ::: "memory")
#define CPA_WAIT1()  asm volatile("cp.async.wait_group 1;" ::: "memory")

// fp32 pair -> (hi, lo) packed bf16x2
__device__ __forceinline__ void split2(float a, float b, uint32_t& hi, uint32_t& lo) {
    __nv_bfloat162 H = __floats2bfloat162_rn(a, b);
    float2 hf = __bfloat1622float2(H);
    __nv_bfloat162 L = __floats2bfloat162_rn(a - hf.x, b - hf.y);
    hi = *reinterpret_cast<uint32_t*>(&H);
    lo = *reinterpret_cast<uint32_t*>(&L);
}

// ---------------- Precompute kernels ----------------
__global__ void ksplit_kernel(const float* __restrict__ K) {
    const int i = blockIdx.x * blockDim.x + threadIdx.x;   // over float4s
    float4 v = ((const float4*)K)[i];
    uint32_t h0, l0, h1, l1;
    split2(v.x, v.y, h0, l0);
    split2(v.z, v.w, h1, l1);
    ((uint2*)gKhi)[i] = make_uint2(h0, h1);
    ((uint2*)gKlo)[i] = make_uint2(l0, l1);
}

__global__ void vtsplit_kernel(const float* __restrict__ V) {
    __shared__ float tile[32][33];
    const int b  = blockIdx.z;
    const int k0 = blockIdx.x * 32;
    const int d0 = blockIdx.y * 32;
    const int tx = threadIdx.x, ty = threadIdx.y;   // (32, 8)
    #pragma unroll
    for (int i = 0; i < 4; ++i)
        tile[ty + 8 * i][tx] = V[((size_t)b * NK + k0 + ty + 8 * i) * DVAL + d0 + tx];
    __syncthreads();
    #pragma unroll
    for (int i = 0; i < 4; ++i) {
        int dvl = ty + 8 * i;
        float x = tile[tx][dvl];
        __nv_bfloat16 h = __float2bfloat16_rn(x);
        __nv_bfloat16 l = __float2bfloat16_rn(x - __bfloat162float(h));
        size_t idx = ((size_t)b * DVAL + d0 + dvl) * NK + k0 + tx;
        gVThi[idx] = h;
        gVTlo[idx] = l;
    }
}

// ---------------- Tile prefetch (all 128 threads) ----------------
__device__ __forceinline__ void issue_tile(uint32_t base, int st, int tid, int n0,
                                           const __nv_bfloat16* __restrict__ gkh,
                                           const __nv_bfloat16* __restrict__ gkl,
                                           const __nv_bfloat16* __restrict__ gvh,
                                           const __nv_bfloat16* __restrict__ gvl) {
    const uint32_t sb = base + st * STAGE;
    #pragma unroll
    for (int i = 0; i < 4; ++i) {              // K hi/lo: 32 keys x 256 B
        int c = tid + NTHREADS * i;            // 0..511
        int key = c >> 4, seg = c & 15;
        uint32_t dst = sb + SKHI + key * KROW + seg * 16;
        CPA16(dst,        gkh + (size_t)(n0 + key) * DIM + seg * 8);
        CPA16(dst + 8704, gkl + (size_t)(n0 + key) * DIM + seg * 8);
    }
    #pragma unroll
    for (int i = 0; i < 4; ++i) {              // VT hi/lo: 128 dv x 64 B
        int c = tid + NTHREADS * i;
        int dv = c >> 2, seg = c & 3;
        uint32_t dst = sb + SVTHI + dv * VROW + seg * 16;
        CPA16(dst,         gvh + (size_t)dv * NK + n0 + seg * 8);
        CPA16(dst + 10240, gvl + (size_t)dv * NK + n0 + seg * 8);
    }
}

// ---------------- Main attention kernel ----------------
__global__ __launch_bounds__(NTHREADS, 3)
void fa_mma_kernel(const float* __restrict__ Q, const int* __restrict__ VL,
                   float* __restrict__ O)
{
    extern __shared__ char smem[];
    const uint32_t base = smem_u32(smem);
    const int tid  = threadIdx.x;
    const int warp = tid >> 5;
    const int lane = tid & 31;
    const int b    = blockIdx.x;        // batch fast -> heavy batches spread over waves
    const int q0   = blockIdx.y * BM;
    const int vlen = VL[b];
    const int nt   = (vlen + BN - 1) / BN;

    const __nv_bfloat16* gkh = gKhi  + (size_t)b * NK * DIM;
    const __nv_bfloat16* gkl = gKlo  + (size_t)b * NK * DIM;
    const __nv_bfloat16* gvh = gVThi + (size_t)b * DVAL * NK;
    const __nv_bfloat16* gvl = gVTlo + (size_t)b * DVAL * NK;

    // ---- Prologue: tile 0 -> stage 0 (async) while Q stages into stage-1 area ----
    issue_tile(base, 0, tid, 0, gkh, gkl, gvh, gvl);
    CPA_COMMIT();

    {
        const int row  = tid >> 1;
        const int colh = (tid & 1) * 64;
        const float4* src = (const float4*)(Q + ((size_t)b * NQ + q0 + row) * DIM + colh);
        const float scale = 0.08838834764831845f;  // 1/sqrt(128)
        #pragma unroll
        for (int i = 0; i < 16; ++i) {
            float4 v = src[i];
            uint32_t h0, l0, h1, l1;
            split2(v.x * scale, v.y * scale, h0, l0);
            split2(v.z * scale, v.w * scale, h1, l1);
            int byte = row * KROW + (colh + i * 4) * 2;
            *(uint32_t*)(smem + SQH + byte)     = h0;
            *(uint32_t*)(smem + SQH + byte + 4) = h1;
            *(uint32_t*)(smem + SQL + byte)     = l0;
            *(uint32_t*)(smem + SQL + byte + 4) = l1;
        }
    }
    __syncthreads();

    // ---- Loop-invariant Q A-fragments (8 k-steps, hi+lo) ----
    uint32_t qh[8][4], ql[8][4];
    {
        const int r  = warp * 16 + (lane >> 2);
        const int cb = 4 * (lane & 3);
        #pragma unroll
        for (int ks = 0; ks < 8; ++ks) {
            int o0 = r * KROW + ks * 32 + cb;
            int o1 = o0 + 8 * KROW;
            qh[ks][0] = *(uint32_t*)(smem + SQH + o0);
            qh[ks][1] = *(uint32_t*)(smem + SQH + o1);
            qh[ks][2] = *(uint32_t*)(smem + SQH + o0 + 16);
            qh[ks][3] = *(uint32_t*)(smem + SQH + o1 + 16);
            ql[ks][0] = *(uint32_t*)(smem + SQL + o0);
            ql[ks][1] = *(uint32_t*)(smem + SQL + o1);
            ql[ks][2] = *(uint32_t*)(smem + SQL + o0 + 16);
            ql[ks][3] = *(uint32_t*)(smem + SQL + o1 + 16);
        }
    }

    float o[16][4];
    #pragma unroll
    for (int j = 0; j < 16; ++j)
        #pragma unroll
        for (int c = 0; c < 4; ++c) o[j][c] = 0.0f;
    float lsum0 = 0.0f, lsum1 = 0.0f;

    // ---- Pipelined KV loop: tile i computes while tile i+1 streams in ----
    for (int it = 0; it < nt; ++it) {
        __syncthreads();   // everyone done with buf[(it+1)&1] (and Q frags at it=0)
        if (it + 1 < nt)
            issue_tile(base, (it + 1) & 1, tid, (it + 1) * BN, gkh, gkl, gvh, gvl);
        CPA_COMMIT();
        CPA_WAIT1();       // tile it resident
        __syncthreads();

        const uint32_t sb = base + (it & 1) * STAGE;
        const int n0 = it * BN;
        const int limit = vlen - n0;

        // ---- GEMM1 (3-term, 3 independent accumulator chains) + softmax ----
        uint32_t pah[2][4], pal[2][4];
        #pragma unroll
        for (int j = 0; j < 4; ++j) {
            float sa[4]  = {0.f, 0.f, 0.f, 0.f};
            float sbx[4] = {0.f, 0.f, 0.f, 0.f};
            float sc[4]  = {0.f, 0.f, 0.f, 0.f};
            #pragma unroll
            for (int kp = 0; kp < 4; ++kp) {
                uint32_t addr = sb + SKHI + (j * 8 + (lane & 7)) * KROW
                              + (kp * 32 + (lane >> 3) * 8) * 2;
                uint32_t bh[4], bl[4];
                ldsm4(bh, addr);
                ldsm4(bl, addr + 8704);
                int ks = kp * 2;
                mma16816(sa,  qh[ks],     bh[0], bh[1]);
                mma16816(sbx, ql[ks],     bh[0], bh[1]);
                mma16816(sc,  qh[ks],     bl[0], bl[1]);
                mma16816(sa,  qh[ks + 1], bh[2], bh[3]);
                mma16816(sbx, ql[ks + 1], bh[2], bh[3]);
                mma16816(sc,  qh[ks + 1], bl[2], bl[3]);
            }
            const int colb = j * 8 + 2 * (lane & 3);
            float s0 = sa[0] + sbx[0] + sc[0];
            float s1 = sa[1] + sbx[1] + sc[1];
            float s2 = sa[2] + sbx[2] + sc[2];
            float s3 = sa[3] + sbx[3] + sc[3];
            float p0 = (colb     < limit) ? __expf(s0) : 0.0f;
            float p1 = (colb + 1 < limit) ? __expf(s1) : 0.0f;
            float p2 = (colb     < limit) ? __expf(s2) : 0.0f;
            float p3 = (colb + 1 < limit) ? __expf(s3) : 0.0f;
            lsum0 += p0 + p1;
            lsum1 += p2 + p3;
            const int kk = j >> 1, ro = (j & 1) * 2;
            split2(p0, p1, pah[kk][ro],     pal[kk][ro]);
            split2(p2, p3, pah[kk][ro + 1], pal[kk][ro + 1]);
        }

        // ---- GEMM2 (3-term): O += Phi@Vhi + Plo@Vhi + Phi@Vlo ----
        #pragma unroll
        for (int j2 = 0; j2 < 16; ++j2) {
            uint32_t addr = sb + SVTHI + (j2 * 8 + (lane & 7)) * VROW
                          + ((lane >> 3) * 8) * 2;
            uint32_t vh[4], vl[4];
            ldsm4(vh, addr);
            ldsm4(vl, addr + 10240);
            mma16816(o[j2], pah[0], vh[0], vh[1]);
            mma16816(o[j2], pal[0], vh[0], vh[1]);
            mma16816(o[j2], pah[0], vl[0], vl[1]);
            mma16816(o[j2], pah[1], vh[2], vh[3]);
            mma16816(o[j2], pal[1], vh[2], vh[3]);
            mma16816(o[j2], pah[1], vl[2], vl[3]);
        }
    }

    // ---- Epilogue ----
    lsum0 += __shfl_xor_sync(0xffffffffu, lsum0, 1);
    lsum0 += __shfl_xor_sync(0xffffffffu, lsum0, 2);
    lsum1 += __shfl_xor_sync(0xffffffffu, lsum1, 1);
    lsum1 += __shfl_xor_sync(0xffffffffu, lsum1, 2);
    const float inv0 = 1.0f / lsum0;
    const float inv1 = 1.0f / lsum1;

    const int rowA = q0 + warp * 16 + (lane >> 2);
    float* OA = O + ((size_t)b * NQ + rowA) * DVAL + 2 * (lane & 3);
    float* OB = OA + 8 * DVAL;
    #pragma unroll
    for (int j2 = 0; j2 < 16; ++j2) {
        float2 a = make_float2(o[j2][0] * inv0, o[j2][1] * inv0);
        float2 c = make_float2(o[j2][2] * inv1, o[j2][3] * inv1);
        *(float2*)(OA + j2 * 8) = a;
        *(float2*)(OB + j2 * 8) = c;
    }
}

extern "C" void kernel_launch(void* const* d_in, const int* in_sizes, int n_in,
                              void* d_out, int out_size)
{
    (void)in_sizes; (void)n_in; (void)out_size;
    const float* Q  = (const float*)d_in[0];
    const float* K  = (const float*)d_in[1];
    const float* V  = (const float*)d_in[2];
    const int*   VL = (const int*)  d_in[3];
    float* O = (float*)d_out;

    static int configured = 0;
    if (!configured) {
        cudaFuncSetAttribute(fa_mma_kernel,
                             cudaFuncAttributeMaxDynamicSharedMemorySize, SM_TOTAL);
        configured = 1;
    }

    ksplit_kernel<<<BATCH * NK * DIM / 4 / 256, 256>>>(K);
    dim3 tg(NK / 32, DVAL / 32, BATCH);
    vtsplit_kernel<<<tg, dim3(32, 8)>>>(V);

    dim3 grid(BATCH, NQ / BM);   // batch as the fast index -> wave-balanced
    fa_mma_kernel<<<grid, NTHREADS, SM_TOTAL>>>(Q, VL, O);
}

// round 7
// speedup vs baseline: 1.0522x; 1.0522x over previous
#include <cuda_runtime.h>
#include <cuda_bf16.h>
#include <cstdint>

// ---------------- Problem constants ----------------
#define BATCH 16
#define NQ    2048
#define NK    2048
#define DIM   128
#define DVAL  128

// ---------------- Tiling ----------------
#define BM 64
#define BN 32
#define NTHREADS 128   // 4 warps; warp w owns q-rows [w*16, w*16+16)

// ---------------- Precomputed split K/V (device globals; allowed scratch) ----------------
__device__ __nv_bfloat16 gKhi[BATCH * NK * DIM];     // [b][key][d]
__device__ __nv_bfloat16 gKlo[BATCH * NK * DIM];
__device__ __nv_bfloat16 gVThi[BATCH * DVAL * NK];   // [b][dv][key]  (transposed)
__device__ __nv_bfloat16 gVTlo[BATCH * DVAL * NK];

// ---------------- SMEM layout (bytes) ----------------
// Per stage:
//   K tile : 32 keys x 128 d bf16 hi+lo, padded row = 272 B (conflict-free ldmatrix)
//   VT tile: 128 dv x 32 keys bf16 hi+lo, padded row = 80 B
#define KROW 272
#define VROW 80
#define SKHI  0
#define SKLO  8704
#define SVTHI 17408
#define SVTLO 27648
#define STAGE 37888
#define SM_TOTAL (2 * STAGE)       // 75776 B -> 2 CTAs/SM

// Q staging area inside stage-1 region (prologue only; tile 1 arrives later)
#define SQH STAGE                  // 37888
#define SQL (STAGE + 17408)        // 55296 ; ends 72704 <= 75776 ✓

// ---------------- PTX helpers ----------------
__device__ __forceinline__ uint32_t smem_u32(const void* p) {
    uint32_t a;
    asm("{ .reg .u64 t; cvta.to.shared.u64 t, %1; cvt.u32.u64 %0, t; }" : "=r"(a) : "l"(p));
    return a;
}
__device__ __forceinline__ void ldsm4(uint32_t* r, uint32_t addr) {
    asm volatile("ldmatrix.sync.aligned.m8n8.x4.shared.b16 {%0,%1,%2,%3}, [%4];"
                 : "=r"(r[0]), "=r"(r[1]), "=r"(r[2]), "=r"(r[3]) : "r"(addr));
}
__device__ __forceinline__ void mma16816(float* c, const uint32_t* a, uint32_t b0, uint32_t b1) {
    asm volatile("mma.sync.aligned.m16n8k16.row.col.f32.bf16.bf16.f32 "
                 "{%0,%1,%2,%3}, {%4,%5,%6,%7}, {%8,%9}, {%0,%1,%2,%3};"
                 : "+f"(c[0]), "+f"(c[1]), "+f"(c[2]), "+f"(c[3])
                 : "r"(a[0]), "r"(a[1]), "r"(a[2]), "r"(a[3]), "r"(b0), "r"(b1));
}
#define CPA16(dst, src) \
    asm volatile("cp.async.cg.shared.global [%0], [%1], 16;" :: "r"(dst), "l"(src))
#define CPA_COMMIT() asm volatile("cp.async.commit_group;" ::: "memory")
#define CPA_WAIT1()  asm volatile("cp.async.wait_group 1;" ::: "memory")

// fp32 pair -> (hi, lo) packed bf16x2
__device__ __forceinline__ void split2(float a, float b, uint32_t& hi, uint32_t& lo) {
    __nv_bfloat162 H = __floats2bfloat162_rn(a, b);
    float2 hf = __bfloat1622float2(H);
    __nv_bfloat162 L = __floats2bfloat162_rn(a - hf.x, b - hf.y);
    hi = *reinterpret_cast<uint32_t*>(&H);
    lo = *reinterpret_cast<uint32_t*>(&L);
}

// ---------------- Precompute kernels ----------------
__global__ void ksplit_kernel(const float* __restrict__ K) {
    const int i = blockIdx.x * blockDim.x + threadIdx.x;   // over float4s
    float4 v = ((const float4*)K)[i];
    uint32_t h0, l0, h1, l1;
    split2(v.x, v.y, h0, l0);
    split2(v.z, v.w, h1, l1);
    ((uint2*)gKhi)[i] = make_uint2(h0, h1);
    ((uint2*)gKlo)[i] = make_uint2(l0, l1);
}

__global__ void vtsplit_kernel(const float* __restrict__ V) {
    __shared__ float tile[32][33];
    const int b  = blockIdx.z;
    const int k0 = blockIdx.x * 32;
    const int d0 = blockIdx.y * 32;
    const int tx = threadIdx.x, ty = threadIdx.y;   // (32, 8)
    #pragma unroll
    for (int i = 0; i < 4; ++i)
        tile[ty + 8 * i][tx] = V[((size_t)b * NK + k0 + ty + 8 * i) * DVAL + d0 + tx];
    __syncthreads();
    #pragma unroll
    for (int i = 0; i < 4; ++i) {
        int dvl = ty + 8 * i;
        float x = tile[tx][dvl];
        __nv_bfloat16 h = __float2bfloat16_rn(x);
        __nv_bfloat16 l = __float2bfloat16_rn(x - __bfloat162float(h));
        size_t idx = ((size_t)b * DVAL + d0 + dvl) * NK + k0 + tx;
        gVThi[idx] = h;
        gVTlo[idx] = l;
    }
}

// ---------------- Tile prefetch (all 128 threads) ----------------
__device__ __forceinline__ void issue_tile(uint32_t base, int st, int tid, int n0,
                                           const __nv_bfloat16* __restrict__ gkh,
                                           const __nv_bfloat16* __restrict__ gkl,
                                           const __nv_bfloat16* __restrict__ gvh,
                                           const __nv_bfloat16* __restrict__ gvl) {
    const uint32_t sb = base + st * STAGE;
    #pragma unroll
    for (int i = 0; i < 4; ++i) {              // K hi/lo: 32 keys x 256 B
        int c = tid + NTHREADS * i;            // 0..511
        int key = c >> 4, seg = c & 15;
        uint32_t dst = sb + SKHI + key * KROW + seg * 16;
        CPA16(dst,        gkh + (size_t)(n0 + key) * DIM + seg * 8);
        CPA16(dst + 8704, gkl + (size_t)(n0 + key) * DIM + seg * 8);
    }
    #pragma unroll
    for (int i = 0; i < 4; ++i) {              // VT hi/lo: 128 dv x 64 B
        int c = tid + NTHREADS * i;
        int dv = c >> 2, seg = c & 3;
        uint32_t dst = sb + SVTHI + dv * VROW + seg * 16;
        CPA16(dst,         gvh + (size_t)dv * NK + n0 + seg * 8);
        CPA16(dst + 10240, gvl + (size_t)dv * NK + n0 + seg * 8);
    }
}

// ---------------- Main attention kernel ----------------
__global__ __launch_bounds__(NTHREADS, 2)    // occ 2: full reg budget, no spills
void fa_mma_kernel(const float* __restrict__ Q, const int* __restrict__ VL,
                   float* __restrict__ O)
{
    extern __shared__ char smem[];
    const uint32_t base = smem_u32(smem);
    const int tid  = threadIdx.x;
    const int warp = tid >> 5;
    const int lane = tid & 31;
    const int b    = blockIdx.x;        // batch fast -> heavy batches spread over waves
    const int q0   = blockIdx.y * BM;
    const int vlen = VL[b];
    const int nt   = (vlen + BN - 1) / BN;

    const __nv_bfloat16* gkh = gKhi  + (size_t)b * NK * DIM;
    const __nv_bfloat16* gkl = gKlo  + (size_t)b * NK * DIM;
    const __nv_bfloat16* gvh = gVThi + (size_t)b * DVAL * NK;
    const __nv_bfloat16* gvl = gVTlo + (size_t)b * DVAL * NK;

    // ---- Prologue: tile 0 -> stage 0 (async) while Q stages into stage-1 area ----
    issue_tile(base, 0, tid, 0, gkh, gkl, gvh, gvl);
    CPA_COMMIT();

    {
        const int row  = tid >> 1;
        const int colh = (tid & 1) * 64;
        const float4* src = (const float4*)(Q + ((size_t)b * NQ + q0 + row) * DIM + colh);
        const float scale = 0.08838834764831845f;  // 1/sqrt(128)
        #pragma unroll
        for (int i = 0; i < 16; ++i) {
            float4 v = src[i];
            uint32_t h0, l0, h1, l1;
            split2(v.x * scale, v.y * scale, h0, l0);
            split2(v.z * scale, v.w * scale, h1, l1);
            int byte = row * KROW + (colh + i * 4) * 2;
            *(uint32_t*)(smem + SQH + byte)     = h0;
            *(uint32_t*)(smem + SQH + byte + 4) = h1;
            *(uint32_t*)(smem + SQL + byte)     = l0;
            *(uint32_t*)(smem + SQL + byte + 4) = l1;
        }
    }
    __syncthreads();

    // ---- Loop-invariant Q A-fragments (8 k-steps, hi+lo) ----
    uint32_t qh[8][4], ql[8][4];
    {
        const int r  = warp * 16 + (lane >> 2);
        const int cb = 4 * (lane & 3);
        #pragma unroll
        for (int ks = 0; ks < 8; ++ks) {
            int o0 = r * KROW + ks * 32 + cb;
            int o1 = o0 + 8 * KROW;
            qh[ks][0] = *(uint32_t*)(smem + SQH + o0);
            qh[ks][1] = *(uint32_t*)(smem + SQH + o1);
            qh[ks][2] = *(uint32_t*)(smem + SQH + o0 + 16);
            qh[ks][3] = *(uint32_t*)(smem + SQH + o1 + 16);
            ql[ks][0] = *(uint32_t*)(smem + SQL + o0);
            ql[ks][1] = *(uint32_t*)(smem + SQL + o1);
            ql[ks][2] = *(uint32_t*)(smem + SQL + o0 + 16);
            ql[ks][3] = *(uint32_t*)(smem + SQL + o1 + 16);
        }
    }

    float o[16][4];
    #pragma unroll
    for (int j = 0; j < 16; ++j)
        #pragma unroll
        for (int c = 0; c < 4; ++c) o[j][c] = 0.0f;
    float lsum0 = 0.0f, lsum1 = 0.0f;

    // ---- Pipelined KV loop: tile i computes while tile i+1 streams in ----
    for (int it = 0; it < nt; ++it) {
        __syncthreads();   // everyone done with buf[(it+1)&1] (and Q frags at it=0)
        if (it + 1 < nt)
            issue_tile(base, (it + 1) & 1, tid, (it + 1) * BN, gkh, gkl, gvh, gvl);
        CPA_COMMIT();
        CPA_WAIT1();       // tile it resident
        __syncthreads();

        const uint32_t sb = base + (it & 1) * STAGE;
        const int n0 = it * BN;
        const int limit = vlen - n0;

        // ---- GEMM1 (3-term, 3 independent accumulator chains) + softmax ----
        uint32_t pah[2][4], pal[2][4];
        #pragma unroll
        for (int j = 0; j < 4; ++j) {
            float sa[4]  = {0.f, 0.f, 0.f, 0.f};
            float sbx[4] = {0.f, 0.f, 0.f, 0.f};
            float sc[4]  = {0.f, 0.f, 0.f, 0.f};
            #pragma unroll
            for (int kp = 0; kp < 4; ++kp) {
                uint32_t addr = sb + SKHI + (j * 8 + (lane & 7)) * KROW
                              + (kp * 32 + (lane >> 3) * 8) * 2;
                uint32_t bh[4], bl[4];
                ldsm4(bh, addr);
                ldsm4(bl, addr + 8704);
                int ks = kp * 2;
                mma16816(sa,  qh[ks],     bh[0], bh[1]);
                mma16816(sbx, ql[ks],     bh[0], bh[1]);
                mma16816(sc,  qh[ks],     bl[0], bl[1]);
                mma16816(sa,  qh[ks + 1], bh[2], bh[3]);
                mma16816(sbx, ql[ks + 1], bh[2], bh[3]);
                mma16816(sc,  qh[ks + 1], bl[2], bl[3]);
            }
            const int colb = j * 8 + 2 * (lane & 3);
            float s0 = sa[0] + sbx[0] + sc[0];
            float s1 = sa[1] + sbx[1] + sc[1];
            float s2 = sa[2] + sbx[2] + sc[2];
            float s3 = sa[3] + sbx[3] + sc[3];
            float p0 = (colb     < limit) ? __expf(s0) : 0.0f;
            float p1 = (colb + 1 < limit) ? __expf(s1) : 0.0f;
            float p2 = (colb     < limit) ? __expf(s2) : 0.0f;
            float p3 = (colb + 1 < limit) ? __expf(s3) : 0.0f;
            lsum0 += p0 + p1;
            lsum1 += p2 + p3;
            const int kk = j >> 1, ro = (j & 1) * 2;
            split2(p0, p1, pah[kk][ro],     pal[kk][ro]);
            split2(p2, p3, pah[kk][ro + 1], pal[kk][ro + 1]);
        }

        // ---- GEMM2 (3-term): O += Phi@Vhi + Plo@Vhi + Phi@Vlo ----
        #pragma unroll
        for (int j2 = 0; j2 < 16; ++j2) {
            uint32_t addr = sb + SVTHI + (j2 * 8 + (lane & 7)) * VROW
                          + ((lane >> 3) * 8) * 2;
            uint32_t vh[4], vl[4];
            ldsm4(vh, addr);
            ldsm4(vl, addr + 10240);
            mma16816(o[j2], pah[0], vh[0], vh[1]);
            mma16816(o[j2], pal[0], vh[0], vh[1]);
            mma16816(o[j2], pah[0], vl[0], vl[1]);
            mma16816(o[j2], pah[1], vh[2], vh[3]);
            mma16816(o[j2], pal[1], vh[2], vh[3]);
            mma16816(o[j2], pah[1], vl[2], vl[3]);
        }
    }

    // ---- Epilogue ----
    lsum0 += __shfl_xor_sync(0xffffffffu, lsum0, 1);
    lsum0 += __shfl_xor_sync(0xffffffffu, lsum0, 2);
    lsum1 += __shfl_xor_sync(0xffffffffu, lsum1, 1);
    lsum1 += __shfl_xor_sync(0xffffffffu, lsum1, 2);
    const float inv0 = 1.0f / lsum0;
    const float inv1 = 1.0f / lsum1;

    const int rowA = q0 + warp * 16 + (lane >> 2);
    float* OA = O + ((size_t)b * NQ + rowA) * DVAL + 2 * (lane & 3);
    float* OB = OA + 8 * DVAL;
    #pragma unroll
    for (int j2 = 0; j2 < 16; ++j2) {
        float2 a = make_float2(o[j2][0] * inv0, o[j2][1] * inv0);
        float2 c = make_float2(o[j2][2] * inv1, o[j2][3] * inv1);
        *(float2*)(OA + j2 * 8) = a;
        *(float2*)(OB + j2 * 8) = c;
    }
}

extern "C" void kernel_launch(void* const* d_in, const int* in_sizes, int n_in,
                              void* d_out, int out_size)
{
    (void)in_sizes; (void)n_in; (void)out_size;
    const float* Q  = (const float*)d_in[0];
    const float* K  = (const float*)d_in[1];
    const float* V  = (const float*)d_in[2];
    const int*   VL = (const int*)  d_in[3];
    float* O = (float*)d_out;

    static int configured = 0;
    if (!configured) {
        cudaFuncSetAttribute(fa_mma_kernel,
                             cudaFuncAttributeMaxDynamicSharedMemorySize, SM_TOTAL);
        configured = 1;
    }

    ksplit_kernel<<<BATCH * NK * DIM / 4 / 256, 256>>>(K);
    dim3 tg(NK / 32, DVAL / 32, BATCH);
    vtsplit_kernel<<<tg, dim3(32, 8)>>>(V);

    dim3 grid(BATCH, NQ / BM);   // batch as the fast index -> wave-balanced
    fa_mma_kernel<<<grid, NTHREADS, SM_TOTAL>>>(Q, VL, O);
}

// round 8
// speedup vs baseline: 1.3647x; 1.2970x over previous
#include <cuda_runtime.h>
#include <cuda_fp16.h>
#include <cstdint>

// ---------------- Problem constants ----------------
#define BATCH 16
#define NQ    2048
#define NK    2048
#define DIM   128
#define DVAL  128

// ---------------- Tiling ----------------
#define BM 64
#define BN 32
#define NTHREADS 128   // 4 warps; warp w owns q-rows [w*16, w*16+16)

// ---------------- Precomputed split K (fp16 hi/lo) + V (fp16 hi only, transposed) ----------------
__device__ __half gKhi[BATCH * NK * DIM];     // [b][key][d]
__device__ __half gKlo[BATCH * NK * DIM];
__device__ __half gVThi[BATCH * DVAL * NK];   // [b][dv][key]  (transposed)

// ---------------- SMEM layout (bytes) ----------------
// Per stage:
//   K tile : 32 keys x 128 d fp16 hi+lo, padded row = 272 B (conflict-free ldmatrix)
//   VT tile: 128 dv x 32 keys fp16 hi,   padded row = 80 B
#define KROW 272
#define VROW 80
#define SKHI  0
#define SKLO  8704
#define SVTHI 17408
#define STAGE 27648                 // 17408 + 128*80
// Q staging above both stages (prologue-only region)
#define SQH (2 * STAGE)             // 55296
#define SQL (2 * STAGE + 17408)     // 72704
#define SM_TOTAL 90112              // 2 CTAs/SM (180 KB < 228 KB); regs are the real occ-2 cap

// ---------------- PTX helpers ----------------
__device__ __forceinline__ uint32_t smem_u32(const void* p) {
    uint32_t a;
    asm("{ .reg .u64 t; cvta.to.shared.u64 t, %1; cvt.u32.u64 %0, t; }" : "=r"(a) : "l"(p));
    return a;
}
__device__ __forceinline__ void ldsm4(uint32_t* r, uint32_t addr) {
    asm volatile("ldmatrix.sync.aligned.m8n8.x4.shared.b16 {%0,%1,%2,%3}, [%4];"
                 : "=r"(r[0]), "=r"(r[1]), "=r"(r[2]), "=r"(r[3]) : "r"(addr));
}
__device__ __forceinline__ void mma16816(float* c, const uint32_t* a, uint32_t b0, uint32_t b1) {
    asm volatile("mma.sync.aligned.m16n8k16.row.col.f32.f16.f16.f32 "
                 "{%0,%1,%2,%3}, {%4,%5,%6,%7}, {%8,%9}, {%0,%1,%2,%3};"
                 : "+f"(c[0]), "+f"(c[1]), "+f"(c[2]), "+f"(c[3])
                 : "r"(a[0]), "r"(a[1]), "r"(a[2]), "r"(a[3]), "r"(b0), "r"(b1));
}
#define CPA16(dst, src) \
    asm volatile("cp.async.cg.shared.global [%0], [%1], 16;" :: "r"(dst), "l"(src))
#define CPA_COMMIT() asm volatile("cp.async.commit_group;" ::: "memory")
#define CPA_WAIT1()  asm volatile("cp.async.wait_group 1;" ::: "memory")

// fp32 pair -> (hi, lo) packed fp16x2
__device__ __forceinline__ void split2(float a, float b, uint32_t& hi, uint32_t& lo) {
    __half2 H = __floats2half2_rn(a, b);
    float2 hf = __half22float2(H);
    __half2 L = __floats2half2_rn(a - hf.x, b - hf.y);
    hi = *reinterpret_cast<uint32_t*>(&H);
    lo = *reinterpret_cast<uint32_t*>(&L);
}

// ---------------- Precompute kernels ----------------
__global__ void ksplit_kernel(const float* __restrict__ K) {
    const int i = blockIdx.x * blockDim.x + threadIdx.x;   // over float4s
    float4 v = ((const float4*)K)[i];
    uint32_t h0, l0, h1, l1;
    split2(v.x, v.y, h0, l0);
    split2(v.z, v.w, h1, l1);
    ((uint2*)gKhi)[i] = make_uint2(h0, h1);
    ((uint2*)gKlo)[i] = make_uint2(l0, l1);
}

__global__ void vtsplit_kernel(const float* __restrict__ V) {
    __shared__ float tile[32][33];
    const int b  = blockIdx.z;
    const int k0 = blockIdx.x * 32;
    const int d0 = blockIdx.y * 32;
    const int tx = threadIdx.x, ty = threadIdx.y;   // (32, 8)
    #pragma unroll
    for (int i = 0; i < 4; ++i)
        tile[ty + 8 * i][tx] = V[((size_t)b * NK + k0 + ty + 8 * i) * DVAL + d0 + tx];
    __syncthreads();
    #pragma unroll
    for (int i = 0; i < 4; ++i) {
        int dvl = ty + 8 * i;
        gVThi[((size_t)b * DVAL + d0 + dvl) * NK + k0 + tx] =
            __float2half_rn(tile[tx][dvl]);
    }
}

// ---------------- Tile prefetch (all 128 threads) ----------------
__device__ __forceinline__ void issue_tile(uint32_t base, int st, int tid, int n0,
                                           const __half* __restrict__ gkh,
                                           const __half* __restrict__ gkl,
                                           const __half* __restrict__ gvh) {
    const uint32_t sb = base + st * STAGE;
    #pragma unroll
    for (int i = 0; i < 4; ++i) {              // K hi/lo: 32 keys x 256 B
        int c = tid + NTHREADS * i;            // 0..511
        int key = c >> 4, seg = c & 15;
        uint32_t dst = sb + SKHI + key * KROW + seg * 16;
        CPA16(dst,        gkh + (size_t)(n0 + key) * DIM + seg * 8);
        CPA16(dst + 8704, gkl + (size_t)(n0 + key) * DIM + seg * 8);
    }
    #pragma unroll
    for (int i = 0; i < 4; ++i) {              // VT hi: 128 dv x 64 B
        int c = tid + NTHREADS * i;
        int dv = c >> 2, seg = c & 3;
        CPA16(sb + SVTHI + dv * VROW + seg * 16,
              gvh + (size_t)dv * NK + n0 + seg * 8);
    }
}

// ---------------- Main attention kernel ----------------
__global__ __launch_bounds__(NTHREADS, 2)    // occ 2: full reg budget, no spills
void fa_mma_kernel(const float* __restrict__ Q, const int* __restrict__ VL,
                   float* __restrict__ O)
{
    extern __shared__ char smem[];
    const uint32_t base = smem_u32(smem);
    const int tid  = threadIdx.x;
    const int warp = tid >> 5;
    const int lane = tid & 31;
    const int b    = blockIdx.y;        // q-tile-fast grid (R4 champion config)
    const int q0   = blockIdx.x * BM;
    const int vlen = VL[b];
    const int nt   = (vlen + BN - 1) / BN;

    const __half* gkh = gKhi  + (size_t)b * NK * DIM;
    const __half* gkl = gKlo  + (size_t)b * NK * DIM;
    const __half* gvh = gVThi + (size_t)b * DVAL * NK;

    // ---- Prologue: tile 0 -> stage 0 (async) while Q stages above the stages ----
    issue_tile(base, 0, tid, 0, gkh, gkl, gvh);
    CPA_COMMIT();

    {
        const int row  = tid >> 1;
        const int colh = (tid & 1) * 64;
        const float4* src = (const float4*)(Q + ((size_t)b * NQ + q0 + row) * DIM + colh);
        const float scale = 0.08838834764831845f;  // 1/sqrt(128)
        #pragma unroll
        for (int i = 0; i < 16; ++i) {
            float4 v = src[i];
            uint32_t h0, l0, h1, l1;
            split2(v.x * scale, v.y * scale, h0, l0);
            split2(v.z * scale, v.w * scale, h1, l1);
            int byte = row * KROW + (colh + i * 4) * 2;
            *(uint32_t*)(smem + SQH + byte)     = h0;
            *(uint32_t*)(smem + SQH + byte + 4) = h1;
            *(uint32_t*)(smem + SQL + byte)     = l0;
            *(uint32_t*)(smem + SQL + byte + 4) = l1;
        }
    }
    __syncthreads();

    // ---- Loop-invariant Q A-fragments (8 k-steps, hi+lo) ----
    uint32_t qh[8][4], ql[8][4];
    {
        const int r  = warp * 16 + (lane >> 2);
        const int cb = 4 * (lane & 3);
        #pragma unroll
        for (int ks = 0; ks < 8; ++ks) {
            int o0 = r * KROW + ks * 32 + cb;
            int o1 = o0 + 8 * KROW;
            qh[ks][0] = *(uint32_t*)(smem + SQH + o0);
            qh[ks][1] = *(uint32_t*)(smem + SQH + o1);
            qh[ks][2] = *(uint32_t*)(smem + SQH + o0 + 16);
            qh[ks][3] = *(uint32_t*)(smem + SQH + o1 + 16);
            ql[ks][0] = *(uint32_t*)(smem + SQL + o0);
            ql[ks][1] = *(uint32_t*)(smem + SQL + o1);
            ql[ks][2] = *(uint32_t*)(smem + SQL + o0 + 16);
            ql[ks][3] = *(uint32_t*)(smem + SQL + o1 + 16);
        }
    }

    float o[16][4];
    #pragma unroll
    for (int j = 0; j < 16; ++j)
        #pragma unroll
        for (int c = 0; c < 4; ++c) o[j][c] = 0.0f;
    float lsum0 = 0.0f, lsum1 = 0.0f;

    // ---- Pipelined KV loop: tile i computes while tile i+1 streams in ----
    for (int it = 0; it < nt; ++it) {
        __syncthreads();
        if (it + 1 < nt)
            issue_tile(base, (it + 1) & 1, tid, (it + 1) * BN, gkh, gkl, gvh);
        CPA_COMMIT();
        CPA_WAIT1();       // tile it resident
        __syncthreads();

        const uint32_t sb = base + (it & 1) * STAGE;
        const int n0 = it * BN;
        const int limit = vlen - n0;

        // ---- GEMM1 (3-term, fp16) + softmax + P-frag pack ----
        uint32_t pah[2][4], pal[2][4];
        #pragma unroll
        for (int j = 0; j < 4; ++j) {
            float sa[4] = {0.f, 0.f, 0.f, 0.f};
            #pragma unroll
            for (int kp = 0; kp < 4; ++kp) {
                uint32_t addr = sb + SKHI + (j * 8 + (lane & 7)) * KROW
                              + (kp * 32 + (lane >> 3) * 8) * 2;
                uint32_t bh[4], bl[4];
                ldsm4(bh, addr);
                ldsm4(bl, addr + 8704);
                int ks = kp * 2;
                mma16816(sa, qh[ks],     bh[0], bh[1]);
                mma16816(sa, ql[ks],     bh[0], bh[1]);
                mma16816(sa, qh[ks],     bl[0], bl[1]);
                mma16816(sa, qh[ks + 1], bh[2], bh[3]);
                mma16816(sa, ql[ks + 1], bh[2], bh[3]);
                mma16816(sa, qh[ks + 1], bl[2], bl[3]);
            }
            const int colb = j * 8 + 2 * (lane & 3);
            float p0 = (colb     < limit) ? __expf(sa[0]) : 0.0f;
            float p1 = (colb + 1 < limit) ? __expf(sa[1]) : 0.0f;
            float p2 = (colb     < limit) ? __expf(sa[2]) : 0.0f;
            float p3 = (colb + 1 < limit) ? __expf(sa[3]) : 0.0f;
            lsum0 += p0 + p1;
            lsum1 += p2 + p3;
            const int kk = j >> 1, ro = (j & 1) * 2;
            split2(p0, p1, pah[kk][ro],     pal[kk][ro]);
            split2(p2, p3, pah[kk][ro + 1], pal[kk][ro + 1]);
        }

        // ---- GEMM2 (2-term fp16): O += (Phi + Plo) @ Vhi ----
        #pragma unroll
        for (int j2 = 0; j2 < 16; ++j2) {
            uint32_t addr = sb + SVTHI + (j2 * 8 + (lane & 7)) * VROW
                          + ((lane >> 3) * 8) * 2;
            uint32_t vh[4];
            ldsm4(vh, addr);
            mma16816(o[j2], pah[0], vh[0], vh[1]);
            mma16816(o[j2], pal[0], vh[0], vh[1]);
            mma16816(o[j2], pah[1], vh[2], vh[3]);
            mma16816(o[j2], pal[1], vh[2], vh[3]);
        }
    }

    // ---- Epilogue ----
    lsum0 += __shfl_xor_sync(0xffffffffu, lsum0, 1);
    lsum0 += __shfl_xor_sync(0xffffffffu, lsum0, 2);
    lsum1 += __shfl_xor_sync(0xffffffffu, lsum1, 1);
    lsum1 += __shfl_xor_sync(0xffffffffu, lsum1, 2);
    const float inv0 = 1.0f / lsum0;
    const float inv1 = 1.0f / lsum1;

    const int rowA = q0 + warp * 16 + (lane >> 2);
    float* OA = O + ((size_t)b * NQ + rowA) * DVAL + 2 * (lane & 3);
    float* OB = OA + 8 * DVAL;
    #pragma unroll
    for (int j2 = 0; j2 < 16; ++j2) {
        float2 a = make_float2(o[j2][0] * inv0, o[j2][1] * inv0);
        float2 c = make_float2(o[j2][2] * inv1, o[j2][3] * inv1);
        *(float2*)(OA + j2 * 8) = a;
        *(float2*)(OB + j2 * 8) = c;
    }
}

extern "C" void kernel_launch(void* const* d_in, const int* in_sizes, int n_in,
                              void* d_out, int out_size)
{
    (void)in_sizes; (void)n_in; (void)out_size;
    const float* Q  = (const float*)d_in[0];
    const float* K  = (const float*)d_in[1];
    const float* V  = (const float*)d_in[2];
    const int*   VL = (const int*)  d_in[3];
    float* O = (float*)d_out;

    static int configured = 0;
    if (!configured) {
        cudaFuncSetAttribute(fa_mma_kernel,
                             cudaFuncAttributeMaxDynamicSharedMemorySize, SM_TOTAL);
        configured = 1;
    }

    ksplit_kernel<<<BATCH * NK * DIM / 4 / 256, 256>>>(K);
    dim3 tg(NK / 32, DVAL / 32, BATCH);
    vtsplit_kernel<<<tg, dim3(32, 8)>>>(V);

    dim3 grid(NQ / BM, BATCH);   // q-tile-fast (R4 champion config)
    fa_mma_kernel<<<grid, NTHREADS, SM_TOTAL>>>(Q, VL, O);
}

// round 9
// speedup vs baseline: 1.9065x; 1.3970x over previous
#include <cuda_runtime.h>
#include <cuda_fp16.h>
#include <cstdint>

// ---------------- Problem constants ----------------
#define BATCH 16
#define NQ    2048
#define NK    2048
#define DIM   128
#define DVAL  128

// ---------------- Tiling ----------------
#define BM 64
#define BN 32
#define NTHREADS 128   // 4 warps; warp w owns q-rows [w*16, w*16+16)

// ---------------- Precomputed fp16 K (hi only) + V (hi only, transposed) ----------------
__device__ __half gKhi[BATCH * NK * DIM];     // [b][key][d]
__device__ __half gVThi[BATCH * DVAL * NK];   // [b][dv][key]  (transposed)

// ---------------- SMEM layout (bytes) ----------------
// Per stage:
//   K tile : 32 keys x 128 d fp16, padded row = 272 B (conflict-free ldmatrix)
//   VT tile: 128 dv x 32 keys fp16, padded row = 80 B
#define KROW 272
#define VROW 80
#define SKHI  0
#define SVTHI 8704
#define STAGE 18944                 // 8704 + 128*80
// Q staging above both stages (prologue-only region; Q stays hi+lo)
#define SQH (2 * STAGE)             // 37888
#define SQL (2 * STAGE + 17408)     // 55296
#define SM_TOTAL 72704              // 2 CTAs/SM (145 KB); regs remain the occ cap

// ---------------- PTX helpers ----------------
__device__ __forceinline__ uint32_t smem_u32(const void* p) {
    uint32_t a;
    asm("{ .reg .u64 t; cvta.to.shared.u64 t, %1; cvt.u32.u64 %0, t; }" : "=r"(a) : "l"(p));
    return a;
}
__device__ __forceinline__ void ldsm4(uint32_t* r, uint32_t addr) {
    asm volatile("ldmatrix.sync.aligned.m8n8.x4.shared.b16 {%0,%1,%2,%3}, [%4];"
                 : "=r"(r[0]), "=r"(r[1]), "=r"(r[2]), "=r"(r[3]) : "r"(addr));
}
__device__ __forceinline__ void mma16816(float* c, const uint32_t* a, uint32_t b0, uint32_t b1) {
    asm volatile("mma.sync.aligned.m16n8k16.row.col.f32.f16.f16.f32 "
                 "{%0,%1,%2,%3}, {%4,%5,%6,%7}, {%8,%9}, {%0,%1,%2,%3};"
                 : "+f"(c[0]), "+f"(c[1]), "+f"(c[2]), "+f"(c[3])
                 : "r"(a[0]), "r"(a[1]), "r"(a[2]), "r"(a[3]), "r"(b0), "r"(b1));
}
#define CPA16(dst, src) \
    asm volatile("cp.async.cg.shared.global [%0], [%1], 16;" :: "r"(dst), "l"(src))
#define CPA_COMMIT() asm volatile("cp.async.commit_group;" ::: "memory")
#define CPA_WAIT1()  asm volatile("cp.async.wait_group 1;" ::: "memory")

// fp32 pair -> (hi, lo) packed fp16x2
__device__ __forceinline__ void split2(float a, float b, uint32_t& hi, uint32_t& lo) {
    __half2 H = __floats2half2_rn(a, b);
    float2 hf = __half22float2(H);
    __half2 L = __floats2half2_rn(a - hf.x, b - hf.y);
    hi = *reinterpret_cast<uint32_t*>(&H);
    lo = *reinterpret_cast<uint32_t*>(&L);
}

// ---------------- Precompute kernels ----------------
__global__ void kconv_kernel(const float* __restrict__ K) {
    const int i = blockIdx.x * blockDim.x + threadIdx.x;   // over float4s
    float4 v = ((const float4*)K)[i];
    __half2 h0 = __floats2half2_rn(v.x, v.y);
    __half2 h1 = __floats2half2_rn(v.z, v.w);
    ((uint2*)gKhi)[i] = make_uint2(*reinterpret_cast<uint32_t*>(&h0),
                                   *reinterpret_cast<uint32_t*>(&h1));
}

__global__ void vtconv_kernel(const float* __restrict__ V) {
    __shared__ float tile[32][33];
    const int b  = blockIdx.z;
    const int k0 = blockIdx.x * 32;
    const int d0 = blockIdx.y * 32;
    const int tx = threadIdx.x, ty = threadIdx.y;   // (32, 8)
    #pragma unroll
    for (int i = 0; i < 4; ++i)
        tile[ty + 8 * i][tx] = V[((size_t)b * NK + k0 + ty + 8 * i) * DVAL + d0 + tx];
    __syncthreads();
    #pragma unroll
    for (int i = 0; i < 4; ++i) {
        int dvl = ty + 8 * i;
        gVThi[((size_t)b * DVAL + d0 + dvl) * NK + k0 + tx] =
            __float2half_rn(tile[tx][dvl]);
    }
}

// ---------------- Tile prefetch (all 128 threads) ----------------
__device__ __forceinline__ void issue_tile(uint32_t base, int st, int tid, int n0,
                                           const __half* __restrict__ gkh,
                                           const __half* __restrict__ gvh) {
    const uint32_t sb = base + st * STAGE;
    #pragma unroll
    for (int i = 0; i < 4; ++i) {              // K hi: 32 keys x 256 B
        int c = tid + NTHREADS * i;            // 0..511
        int key = c >> 4, seg = c & 15;
        CPA16(sb + SKHI + key * KROW + seg * 16,
              gkh + (size_t)(n0 + key) * DIM + seg * 8);
    }
    #pragma unroll
    for (int i = 0; i < 4; ++i) {              // VT hi: 128 dv x 64 B
        int c = tid + NTHREADS * i;
        int dv = c >> 2, seg = c & 3;
        CPA16(sb + SVTHI + dv * VROW + seg * 16,
              gvh + (size_t)dv * NK + n0 + seg * 8);
    }
}

// ---------------- Main attention kernel ----------------
__global__ __launch_bounds__(NTHREADS, 2)    // occ 2: full reg budget, no spills
void fa_mma_kernel(const float* __restrict__ Q, const int* __restrict__ VL,
                   float* __restrict__ O)
{
    extern __shared__ char smem[];
    const uint32_t base = smem_u32(smem);
    const int tid  = threadIdx.x;
    const int warp = tid >> 5;
    const int lane = tid & 31;
    const int b    = blockIdx.y;        // q-tile-fast grid (champion config)
    const int q0   = blockIdx.x * BM;
    const int vlen = VL[b];
    const int nt   = (vlen + BN - 1) / BN;

    const __half* gkh = gKhi  + (size_t)b * NK * DIM;
    const __half* gvh = gVThi + (size_t)b * DVAL * NK;

    // ---- Prologue: tile 0 -> stage 0 (async) while Q stages above the stages ----
    issue_tile(base, 0, tid, 0, gkh, gvh);
    CPA_COMMIT();

    {
        const int row  = tid >> 1;
        const int colh = (tid & 1) * 64;
        const float4* src = (const float4*)(Q + ((size_t)b * NQ + q0 + row) * DIM + colh);
        const float scale = 0.08838834764831845f;  // 1/sqrt(128)
        #pragma unroll
        for (int i = 0; i < 16; ++i) {
            float4 v = src[i];
            uint32_t h0, l0, h1, l1;
            split2(v.x * scale, v.y * scale, h0, l0);
            split2(v.z * scale, v.w * scale, h1, l1);
            int byte = row * KROW + (colh + i * 4) * 2;
            *(uint32_t*)(smem + SQH + byte)     = h0;
            *(uint32_t*)(smem + SQH + byte + 4) = h1;
            *(uint32_t*)(smem + SQL + byte)     = l0;
            *(uint32_t*)(smem + SQL + byte + 4) = l1;
        }
    }
    __syncthreads();

    // ---- Loop-invariant Q A-fragments (8 k-steps, hi+lo) ----
    uint32_t qh[8][4], ql[8][4];
    {
        const int r  = warp * 16 + (lane >> 2);
        const int cb = 4 * (lane & 3);
        #pragma unroll
        for (int ks = 0; ks < 8; ++ks) {
            int o0 = r * KROW + ks * 32 + cb;
            int o1 = o0 + 8 * KROW;
            qh[ks][0] = *(uint32_t*)(smem + SQH + o0);
            qh[ks][1] = *(uint32_t*)(smem + SQH + o1);
            qh[ks][2] = *(uint32_t*)(smem + SQH + o0 + 16);
            qh[ks][3] = *(uint32_t*)(smem + SQH + o1 + 16);
            ql[ks][0] = *(uint32_t*)(smem + SQL + o0);
            ql[ks][1] = *(uint32_t*)(smem + SQL + o1);
            ql[ks][2] = *(uint32_t*)(smem + SQL + o0 + 16);
            ql[ks][3] = *(uint32_t*)(smem + SQL + o1 + 16);
        }
    }

    float o[16][4];
    #pragma unroll
    for (int j = 0; j < 16; ++j)
        #pragma unroll
        for (int c = 0; c < 4; ++c) o[j][c] = 0.0f;
    float lsum0 = 0.0f, lsum1 = 0.0f;

    // ---- Pipelined KV loop: tile i computes while tile i+1 streams in ----
    for (int it = 0; it < nt; ++it) {
        __syncthreads();
        if (it + 1 < nt)
            issue_tile(base, (it + 1) & 1, tid, (it + 1) * BN, gkh, gvh);
        CPA_COMMIT();
        CPA_WAIT1();       // tile it resident
        __syncthreads();

        const uint32_t sb = base + (it & 1) * STAGE;
        const int n0 = it * BN;
        const int limit = vlen - n0;

        // ---- GEMM1 (2-term: (Qhi + Qlo) @ Khi) + softmax + P-frag pack ----
        uint32_t pah[2][4], pal[2][4];
        #pragma unroll
        for (int j = 0; j < 4; ++j) {
            float sa[4] = {0.f, 0.f, 0.f, 0.f};
            #pragma unroll
            for (int kp = 0; kp < 4; ++kp) {
                uint32_t addr = sb + SKHI + (j * 8 + (lane & 7)) * KROW
                              + (kp * 32 + (lane >> 3) * 8) * 2;
                uint32_t bh[4];
                ldsm4(bh, addr);
                int ks = kp * 2;
                mma16816(sa, qh[ks],     bh[0], bh[1]);
                mma16816(sa, ql[ks],     bh[0], bh[1]);
                mma16816(sa, qh[ks + 1], bh[2], bh[3]);
                mma16816(sa, ql[ks + 1], bh[2], bh[3]);
            }
            const int colb = j * 8 + 2 * (lane & 3);
            float p0 = (colb     < limit) ? __expf(sa[0]) : 0.0f;
            float p1 = (colb + 1 < limit) ? __expf(sa[1]) : 0.0f;
            float p2 = (colb     < limit) ? __expf(sa[2]) : 0.0f;
            float p3 = (colb + 1 < limit) ? __expf(sa[3]) : 0.0f;
            lsum0 += p0 + p1;
            lsum1 += p2 + p3;
            const int kk = j >> 1, ro = (j & 1) * 2;
            split2(p0, p1, pah[kk][ro],     pal[kk][ro]);
            split2(p2, p3, pah[kk][ro + 1], pal[kk][ro + 1]);
        }

        // ---- GEMM2 (2-term: (Phi + Plo) @ Vhi) ----
        #pragma unroll
        for (int j2 = 0; j2 < 16; ++j2) {
            uint32_t addr = sb + SVTHI + (j2 * 8 + (lane & 7)) * VROW
                          + ((lane >> 3) * 8) * 2;
            uint32_t vh[4];
            ldsm4(vh, addr);
            mma16816(o[j2], pah[0], vh[0], vh[1]);
            mma16816(o[j2], pal[0], vh[0], vh[1]);
            mma16816(o[j2], pah[1], vh[2], vh[3]);
            mma16816(o[j2], pal[1], vh[2], vh[3]);
        }
    }

    // ---- Epilogue ----
    lsum0 += __shfl_xor_sync(0xffffffffu, lsum0, 1);
    lsum0 += __shfl_xor_sync(0xffffffffu, lsum0, 2);
    lsum1 += __shfl_xor_sync(0xffffffffu, lsum1, 1);
    lsum1 += __shfl_xor_sync(0xffffffffu, lsum1, 2);
    const float inv0 = 1.0f / lsum0;
    const float inv1 = 1.0f / lsum1;

    const int rowA = q0 + warp * 16 + (lane >> 2);
    float* OA = O + ((size_t)b * NQ + rowA) * DVAL + 2 * (lane & 3);
    float* OB = OA + 8 * DVAL;
    #pragma unroll
    for (int j2 = 0; j2 < 16; ++j2) {
        float2 a = make_float2(o[j2][0] * inv0, o[j2][1] * inv0);
        float2 c = make_float2(o[j2][2] * inv1, o[j2][3] * inv1);
        *(float2*)(OA + j2 * 8) = a;
        *(float2*)(OB + j2 * 8) = c;
    }
}

extern "C" void kernel_launch(void* const* d_in, const int* in_sizes, int n_in,
                              void* d_out, int out_size)
{
    (void)in_sizes; (void)n_in; (void)out_size;
    const float* Q  = (const float*)d_in[0];
    const float* K  = (const float*)d_in[1];
    const float* V  = (const float*)d_in[2];
    const int*   VL = (const int*)  d_in[3];
    float* O = (float*)d_out;

    static int configured = 0;
    if (!configured) {
        cudaFuncSetAttribute(fa_mma_kernel,
                             cudaFuncAttributeMaxDynamicSharedMemorySize, SM_TOTAL);
        configured = 1;
    }

    kconv_kernel<<<BATCH * NK * DIM / 4 / 256, 256>>>(K);
    dim3 tg(NK / 32, DVAL / 32, BATCH);
    vtconv_kernel<<<tg, dim3(32, 8)>>>(V);

    dim3 grid(NQ / BM, BATCH);   // q-tile-fast (champion config)
    fa_mma_kernel<<<grid, NTHREADS, SM_TOTAL>>>(Q, VL, O);
}

// round 10
// speedup vs baseline: 2.0851x; 1.0937x over previous
#include <cuda_runtime.h>
#include <cuda_fp16.h>
#include <cstdint>

// ---------------- Problem constants ----------------
#define BATCH 16
#define NQ    2048
#define NK    2048
#define DIM   128
#define DVAL  128

// ---------------- Tiling ----------------
#define BM 64
#define BN 32
#define NTHREADS 128   // 4 warps; warp w owns q-rows [w*16, w*16+16)

// ---------------- Precomputed fp16 K + V (transposed) ----------------
__device__ __half gKhi[BATCH * NK * DIM];     // [b][key][d]
__device__ __half gVThi[BATCH * DVAL * NK];   // [b][dv][key]  (transposed)

// ---------------- SMEM layout (bytes) ----------------
// Per stage:
//   K tile : 32 keys x 128 d fp16, padded row = 272 B (conflict-free ldmatrix)
//   VT tile: 128 dv x 32 keys fp16, padded row = 80 B
#define KROW 272
#define VROW 80
#define SKHI  0
#define SVTHI 8704
#define STAGE 18944                 // 8704 + 128*80
// Q staging above both stages (prologue-only region; Q stays hi+lo)
#define SQH (2 * STAGE)             // 37888
#define SQL (2 * STAGE + 17408)     // 55296
#define SM_TOTAL 72704              // 2 CTAs/SM

// ---------------- PTX helpers ----------------
__device__ __forceinline__ uint32_t smem_u32(const void* p) {
    uint32_t a;
    asm("{ .reg .u64 t; cvta.to.shared.u64 t, %1; cvt.u32.u64 %0, t; }" : "=r"(a) : "l"(p));
    return a;
}
__device__ __forceinline__ void ldsm4(uint32_t* r, uint32_t addr) {
    asm volatile("ldmatrix.sync.aligned.m8n8.x4.shared.b16 {%0,%1,%2,%3}, [%4];"
                 : "=r"(r[0]), "=r"(r[1]), "=r"(r[2]), "=r"(r[3]) : "r"(addr));
}
__device__ __forceinline__ void mma16816(float* c, const uint32_t* a, uint32_t b0, uint32_t b1) {
    asm volatile("mma.sync.aligned.m16n8k16.row.col.f32.f16.f16.f32 "
                 "{%0,%1,%2,%3}, {%4,%5,%6,%7}, {%8,%9}, {%0,%1,%2,%3};"
                 : "+f"(c[0]), "+f"(c[1]), "+f"(c[2]), "+f"(c[3])
                 : "r"(a[0]), "r"(a[1]), "r"(a[2]), "r"(a[3]), "r"(b0), "r"(b1));
}
#define CPA16(dst, src) \
    asm volatile("cp.async.cg.shared.global [%0], [%1], 16;" :: "r"(dst), "l"(src))
#define CPA_COMMIT() asm volatile("cp.async.commit_group;" ::: "memory")
#define CPA_WAIT1()  asm volatile("cp.async.wait_group 1;" ::: "memory")

// fp32 pair -> (hi, lo) packed fp16x2
__device__ __forceinline__ void split2(float a, float b, uint32_t& hi, uint32_t& lo) {
    __half2 H = __floats2half2_rn(a, b);
    float2 hf = __half22float2(H);
    __half2 L = __floats2half2_rn(a - hf.x, b - hf.y);
    hi = *reinterpret_cast<uint32_t*>(&H);
    lo = *reinterpret_cast<uint32_t*>(&L);
}
// fp32 pair -> packed fp16x2 (plain quantization)
__device__ __forceinline__ uint32_t pack2(float a, float b) {
    __half2 H = __floats2half2_rn(a, b);
    return *reinterpret_cast<uint32_t*>(&H);
}

// ---------------- Precompute kernels ----------------
__global__ void kconv_kernel(const float* __restrict__ K) {
    const int i = blockIdx.x * blockDim.x + threadIdx.x;   // over float4s
    float4 v = ((const float4*)K)[i];
    ((uint2*)gKhi)[i] = make_uint2(pack2(v.x, v.y), pack2(v.z, v.w));
}

__global__ void vtconv_kernel(const float* __restrict__ V) {
    __shared__ float tile[32][33];
    const int b  = blockIdx.z;
    const int k0 = blockIdx.x * 32;
    const int d0 = blockIdx.y * 32;
    const int tx = threadIdx.x, ty = threadIdx.y;   // (32, 8)
    #pragma unroll
    for (int i = 0; i < 4; ++i)
        tile[ty + 8 * i][tx] = V[((size_t)b * NK + k0 + ty + 8 * i) * DVAL + d0 + tx];
    __syncthreads();
    #pragma unroll
    for (int i = 0; i < 4; ++i) {
        int dvl = ty + 8 * i;
        gVThi[((size_t)b * DVAL + d0 + dvl) * NK + k0 + tx] =
            __float2half_rn(tile[tx][dvl]);
    }
}

// ---------------- Tile prefetch (all 128 threads) ----------------
__device__ __forceinline__ void issue_tile(uint32_t base, int st, int tid, int n0,
                                           const __half* __restrict__ gkh,
                                           const __half* __restrict__ gvh) {
    const uint32_t sb = base + st * STAGE;
    #pragma unroll
    for (int i = 0; i < 4; ++i) {              // K: 32 keys x 256 B
        int c = tid + NTHREADS * i;            // 0..511
        int key = c >> 4, seg = c & 15;
        CPA16(sb + SKHI + key * KROW + seg * 16,
              gkh + (size_t)(n0 + key) * DIM + seg * 8);
    }
    #pragma unroll
    for (int i = 0; i < 4; ++i) {              // VT: 128 dv x 64 B
        int c = tid + NTHREADS * i;
        int dv = c >> 2, seg = c & 3;
        CPA16(sb + SVTHI + dv * VROW + seg * 16,
              gvh + (size_t)dv * NK + n0 + seg * 8);
    }
}

// ---------------- Main attention kernel ----------------
__global__ __launch_bounds__(NTHREADS, 2)    // occ 2: full reg budget, no spills
void fa_mma_kernel(const float* __restrict__ Q, const int* __restrict__ VL,
                   float* __restrict__ O)
{
    extern __shared__ char smem[];
    const uint32_t base = smem_u32(smem);
    const int tid  = threadIdx.x;
    const int warp = tid >> 5;
    const int lane = tid & 31;
    const int b    = blockIdx.y;        // q-tile-fast grid (champion config)
    const int q0   = blockIdx.x * BM;
    const int vlen = VL[b];
    const int nt   = (vlen + BN - 1) / BN;

    const __half* gkh = gKhi  + (size_t)b * NK * DIM;
    const __half* gvh = gVThi + (size_t)b * DVAL * NK;

    // ---- Prologue: tile 0 -> stage 0 (async) while Q stages above the stages ----
    issue_tile(base, 0, tid, 0, gkh, gvh);
    CPA_COMMIT();

    {
        const int row  = tid >> 1;
        const int colh = (tid & 1) * 64;
        const float4* src = (const float4*)(Q + ((size_t)b * NQ + q0 + row) * DIM + colh);
        const float scale = 0.08838834764831845f;  // 1/sqrt(128)
        #pragma unroll
        for (int i = 0; i < 16; ++i) {
            float4 v = src[i];
            uint32_t h0, l0, h1, l1;
            split2(v.x * scale, v.y * scale, h0, l0);
            split2(v.z * scale, v.w * scale, h1, l1);
            int byte = row * KROW + (colh + i * 4) * 2;
            *(uint32_t*)(smem + SQH + byte)     = h0;
            *(uint32_t*)(smem + SQH + byte + 4) = h1;
            *(uint32_t*)(smem + SQL + byte)     = l0;
            *(uint32_t*)(smem + SQL + byte + 4) = l1;
        }
    }
    __syncthreads();

    // ---- Loop-invariant Q A-fragments (8 k-steps, hi+lo) ----
    uint32_t qh[8][4], ql[8][4];
    {
        const int r  = warp * 16 + (lane >> 2);
        const int cb = 4 * (lane & 3);
        #pragma unroll
        for (int ks = 0; ks < 8; ++ks) {
            int o0 = r * KROW + ks * 32 + cb;
            int o1 = o0 + 8 * KROW;
            qh[ks][0] = *(uint32_t*)(smem + SQH + o0);
            qh[ks][1] = *(uint32_t*)(smem + SQH + o1);
            qh[ks][2] = *(uint32_t*)(smem + SQH + o0 + 16);
            qh[ks][3] = *(uint32_t*)(smem + SQH + o1 + 16);
            ql[ks][0] = *(uint32_t*)(smem + SQL + o0);
            ql[ks][1] = *(uint32_t*)(smem + SQL + o1);
            ql[ks][2] = *(uint32_t*)(smem + SQL + o0 + 16);
            ql[ks][3] = *(uint32_t*)(smem + SQL + o1 + 16);
        }
    }

    float o[16][4];
    #pragma unroll
    for (int j = 0; j < 16; ++j)
        #pragma unroll
        for (int c = 0; c < 4; ++c) o[j][c] = 0.0f;
    float lsum0 = 0.0f, lsum1 = 0.0f;

    // ---- Pipelined KV loop: tile i computes while tile i+1 streams in ----
    for (int it = 0; it < nt; ++it) {
        __syncthreads();
        if (it + 1 < nt)
            issue_tile(base, (it + 1) & 1, tid, (it + 1) * BN, gkh, gvh);
        CPA_COMMIT();
        CPA_WAIT1();       // tile it resident
        __syncthreads();

        const uint32_t sb = base + (it & 1) * STAGE;
        const int n0 = it * BN;
        const int limit = vlen - n0;

        // ---- GEMM1 (2-term: (Qhi + Qlo) @ Khi) + softmax + fp16 P pack ----
        uint32_t pah[2][4];
        #pragma unroll
        for (int j = 0; j < 4; ++j) {
            float sa[4] = {0.f, 0.f, 0.f, 0.f};
            #pragma unroll
            for (int kp = 0; kp < 4; ++kp) {
                uint32_t addr = sb + SKHI + (j * 8 + (lane & 7)) * KROW
                              + (kp * 32 + (lane >> 3) * 8) * 2;
                uint32_t bh[4];
                ldsm4(bh, addr);
                int ks = kp * 2;
                mma16816(sa, qh[ks],     bh[0], bh[1]);
                mma16816(sa, ql[ks],     bh[0], bh[1]);
                mma16816(sa, qh[ks + 1], bh[2], bh[3]);
                mma16816(sa, ql[ks + 1], bh[2], bh[3]);
            }
            const int colb = j * 8 + 2 * (lane & 3);
            float p0 = (colb     < limit) ? __expf(sa[0]) : 0.0f;
            float p1 = (colb + 1 < limit) ? __expf(sa[1]) : 0.0f;
            float p2 = (colb     < limit) ? __expf(sa[2]) : 0.0f;
            float p3 = (colb + 1 < limit) ? __expf(sa[3]) : 0.0f;
            lsum0 += p0 + p1;
            lsum1 += p2 + p3;
            const int kk = j >> 1, ro = (j & 1) * 2;
            pah[kk][ro]     = pack2(p0, p1);
            pah[kk][ro + 1] = pack2(p2, p3);
        }

        // ---- GEMM2 (1-term: Phi @ Vhi) ----
        #pragma unroll
        for (int j2 = 0; j2 < 16; ++j2) {
            uint32_t addr = sb + SVTHI + (j2 * 8 + (lane & 7)) * VROW
                          + ((lane >> 3) * 8) * 2;
            uint32_t vh[4];
            ldsm4(vh, addr);
            mma16816(o[j2], pah[0], vh[0], vh[1]);
            mma16816(o[j2], pah[1], vh[2], vh[3]);
        }
    }

    // ---- Epilogue ----
    lsum0 += __shfl_xor_sync(0xffffffffu, lsum0, 1);
    lsum0 += __shfl_xor_sync(0xffffffffu, lsum0, 2);
    lsum1 += __shfl_xor_sync(0xffffffffu, lsum1, 1);
    lsum1 += __shfl_xor_sync(0xffffffffu, lsum1, 2);
    const float inv0 = 1.0f / lsum0;
    const float inv1 = 1.0f / lsum1;

    const int rowA = q0 + warp * 16 + (lane >> 2);
    float* OA = O + ((size_t)b * NQ + rowA) * DVAL + 2 * (lane & 3);
    float* OB = OA + 8 * DVAL;
    #pragma unroll
    for (int j2 = 0; j2 < 16; ++j2) {
        float2 a = make_float2(o[j2][0] * inv0, o[j2][1] * inv0);
        float2 c = make_float2(o[j2][2] * inv1, o[j2][3] * inv1);
        *(float2*)(OA + j2 * 8) = a;
        *(float2*)(OB + j2 * 8) = c;
    }
}

extern "C" void kernel_launch(void* const* d_in, const int* in_sizes, int n_in,
                              void* d_out, int out_size)
{
    (void)in_sizes; (void)n_in; (void)out_size;
    const float* Q  = (const float*)d_in[0];
    const float* K  = (const float*)d_in[1];
    const float* V  = (const float*)d_in[2];
    const int*   VL = (const int*)  d_in[3];
    float* O = (float*)d_out;

    static int configured = 0;
    if (!configured) {
        cudaFuncSetAttribute(fa_mma_kernel,
                             cudaFuncAttributeMaxDynamicSharedMemorySize, SM_TOTAL);
        configured = 1;
    }

    kconv_kernel<<<BATCH * NK * DIM / 4 / 256, 256>>>(K);
    dim3 tg(NK / 32, DVAL / 32, BATCH);
    vtconv_kernel<<<tg, dim3(32, 8)>>>(V);

    dim3 grid(NQ / BM, BATCH);   // q-tile-fast (champion config)
    fa_mma_kernel<<<grid, NTHREADS, SM_TOTAL>>>(Q, VL, O);
}

// round 11
// speedup vs baseline: 2.5615x; 1.2285x over previous
#include <cuda_runtime.h>
#include <cuda_fp16.h>
#include <cstdint>

// ---------------- Problem constants ----------------
#define BATCH 16
#define NQ    2048
#define NK    2048
#define DIM   128
#define DVAL  128

// ---------------- Tiling ----------------
#define BM 64
#define BN 64
#define NTHREADS 128   // 4 warps; warp w owns q-rows [w*16, w*16+16)

// ---------------- Precomputed fp16 K + V (transposed) ----------------
__device__ __half gK[BATCH * NK * DIM];      // [b][key][d]
__device__ __half gVT[BATCH * DVAL * NK];    // [b][dv][key]  (transposed)

// ---------------- SMEM layout (bytes) ----------------
// Per stage:
//   K tile : 64 keys x 128 d fp16, padded row = 272 B  (banks 4r mod 32: conflict-free)
//   VT tile: 128 dv x 64 keys fp16, padded row = 144 B (banks 4r mod 32: conflict-free)
#define KROW 272
#define VROW 144
#define SK    0
#define SVT   17408                  // 64*272
#define STAGE 35840                  // 17408 + 128*144
// Q staging overlays stage-1 region (prologue only; tile 1 arrives after Q frags are read)
#define SQ    STAGE
#define SM_TOTAL (2 * STAGE)         // 71680 -> 2 CTAs/SM

// ---------------- PTX helpers ----------------
__device__ __forceinline__ uint32_t smem_u32(const void* p) {
    uint32_t a;
    asm("{ .reg .u64 t; cvta.to.shared.u64 t, %1; cvt.u32.u64 %0, t; }" : "=r"(a) : "l"(p));
    return a;
}
__device__ __forceinline__ void ldsm4(uint32_t* r, uint32_t addr) {
    asm volatile("ldmatrix.sync.aligned.m8n8.x4.shared.b16 {%0,%1,%2,%3}, [%4];"
                 : "=r"(r[0]), "=r"(r[1]), "=r"(r[2]), "=r"(r[3]) : "r"(addr));
}
__device__ __forceinline__ void mma16816(float* c, const uint32_t* a, uint32_t b0, uint32_t b1) {
    asm volatile("mma.sync.aligned.m16n8k16.row.col.f32.f16.f16.f32 "
                 "{%0,%1,%2,%3}, {%4,%5,%6,%7}, {%8,%9}, {%0,%1,%2,%3};"
                 : "+f"(c[0]), "+f"(c[1]), "+f"(c[2]), "+f"(c[3])
                 : "r"(a[0]), "r"(a[1]), "r"(a[2]), "r"(a[3]), "r"(b0), "r"(b1));
}
#define CPA16(dst, src) \
    asm volatile("cp.async.cg.shared.global [%0], [%1], 16;" :: "r"(dst), "l"(src))
#define CPA_COMMIT() asm volatile("cp.async.commit_group;" ::: "memory")
#define CPA_WAIT1()  asm volatile("cp.async.wait_group 1;" ::: "memory")

// fp32 pair -> packed fp16x2
__device__ __forceinline__ uint32_t pack2(float a, float b) {
    __half2 H = __floats2half2_rn(a, b);
    return *reinterpret_cast<uint32_t*>(&H);
}

// ---------------- Precompute kernels ----------------
__global__ void kconv_kernel(const float* __restrict__ K) {
    const int i = blockIdx.x * blockDim.x + threadIdx.x;   // over float4s
    float4 v = ((const float4*)K)[i];
    ((uint2*)gK)[i] = make_uint2(pack2(v.x, v.y), pack2(v.z, v.w));
}

__global__ void vtconv_kernel(const float* __restrict__ V) {
    __shared__ float tile[32][33];
    const int b  = blockIdx.z;
    const int k0 = blockIdx.x * 32;
    const int d0 = blockIdx.y * 32;
    const int tx = threadIdx.x, ty = threadIdx.y;   // (32, 8)
    #pragma unroll
    for (int i = 0; i < 4; ++i)
        tile[ty + 8 * i][tx] = V[((size_t)b * NK + k0 + ty + 8 * i) * DVAL + d0 + tx];
    __syncthreads();
    #pragma unroll
    for (int i = 0; i < 4; ++i) {
        int dvl = ty + 8 * i;
        gVT[((size_t)b * DVAL + d0 + dvl) * NK + k0 + tx] =
            __float2half_rn(tile[tx][dvl]);
    }
}

// ---------------- Tile prefetch (all 128 threads; 16 CPA16 each) ----------------
__device__ __forceinline__ void issue_tile(uint32_t base, int st, int tid, int n0,
                                           const __half* __restrict__ gk,
                                           const __half* __restrict__ gvt) {
    const uint32_t sb = base + st * STAGE;
    #pragma unroll
    for (int i = 0; i < 8; ++i) {              // K: 64 keys x 256 B = 1024 chunks
        int c = tid + NTHREADS * i;
        int key = c >> 4, seg = c & 15;
        CPA16(sb + SK + key * KROW + seg * 16,
              gk + (size_t)(n0 + key) * DIM + seg * 8);
    }
    #pragma unroll
    for (int i = 0; i < 8; ++i) {              // VT: 128 dv x 128 B = 1024 chunks
        int c = tid + NTHREADS * i;
        int dv = c >> 3, seg = c & 7;
        CPA16(sb + SVT + dv * VROW + seg * 16,
              gvt + (size_t)dv * NK + n0 + seg * 8);
    }
}

// ---------------- Main attention kernel ----------------
__global__ __launch_bounds__(NTHREADS, 2)
void fa_mma_kernel(const float* __restrict__ Q, const int* __restrict__ VL,
                   float* __restrict__ O)
{
    extern __shared__ char smem[];
    const uint32_t base = smem_u32(smem);
    const int tid  = threadIdx.x;
    const int warp = tid >> 5;
    const int lane = tid & 31;
    const int b    = blockIdx.y;        // q-tile-fast grid (champion config)
    const int q0   = blockIdx.x * BM;
    const int vlen = VL[b];
    const int nt   = (vlen + BN - 1) / BN;

    const __half* gk  = gK  + (size_t)b * NK * DIM;
    const __half* gvt = gVT + (size_t)b * DVAL * NK;

    // ---- Prologue: tile 0 -> stage 0 (async) while Q (fp16) stages into stage-1 area ----
    issue_tile(base, 0, tid, 0, gk, gvt);
    CPA_COMMIT();

    {
        const int row  = tid >> 1;
        const int colh = (tid & 1) * 64;
        const float4* src = (const float4*)(Q + ((size_t)b * NQ + q0 + row) * DIM + colh);
        const float scale = 0.08838834764831845f;  // 1/sqrt(128)
        #pragma unroll
        for (int i = 0; i < 16; ++i) {
            float4 v = src[i];
            int byte = row * KROW + (colh + i * 4) * 2;
            *(uint32_t*)(smem + SQ + byte)     = pack2(v.x * scale, v.y * scale);
            *(uint32_t*)(smem + SQ + byte + 4) = pack2(v.z * scale, v.w * scale);
        }
    }
    __syncthreads();

    // ---- Loop-invariant Q A-fragments (8 k-steps) ----
    uint32_t qh[8][4];
    {
        const int r  = warp * 16 + (lane >> 2);
        const int cb = 4 * (lane & 3);
        #pragma unroll
        for (int ks = 0; ks < 8; ++ks) {
            int o0 = r * KROW + ks * 32 + cb;
            int o1 = o0 + 8 * KROW;
            qh[ks][0] = *(uint32_t*)(smem + SQ + o0);
            qh[ks][1] = *(uint32_t*)(smem + SQ + o1);
            qh[ks][2] = *(uint32_t*)(smem + SQ + o0 + 16);
            qh[ks][3] = *(uint32_t*)(smem + SQ + o1 + 16);
        }
    }

    float o[16][4];
    #pragma unroll
    for (int j = 0; j < 16; ++j)
        #pragma unroll
        for (int c = 0; c < 4; ++c) o[j][c] = 0.0f;
    float lsum0 = 0.0f, lsum1 = 0.0f;

    // ---- Pipelined KV loop (BN=64): tile i computes while tile i+1 streams in ----
    for (int it = 0; it < nt; ++it) {
        __syncthreads();   // all warps done with buf[(it+1)&1] (and Q frags at it=0)
        if (it + 1 < nt)
            issue_tile(base, (it + 1) & 1, tid, (it + 1) * BN, gk, gvt);
        CPA_COMMIT();
        CPA_WAIT1();       // tile it resident
        __syncthreads();

        const uint32_t sb = base + (it & 1) * STAGE;
        const int n0 = it * BN;
        const int limit = vlen - n0;

        // ---- GEMM1 (1-term fp16: Q @ K^T) + softmax + fp16 P pack ----
        uint32_t pah[4][4];
        #pragma unroll
        for (int j = 0; j < 8; ++j) {
            float sa[4] = {0.f, 0.f, 0.f, 0.f};
            #pragma unroll
            for (int kp = 0; kp < 4; ++kp) {
                uint32_t addr = sb + SK + (j * 8 + (lane & 7)) * KROW
                              + (kp * 32 + (lane >> 3) * 8) * 2;
                uint32_t bh[4];
                ldsm4(bh, addr);
                mma16816(sa, qh[kp * 2],     bh[0], bh[1]);
                mma16816(sa, qh[kp * 2 + 1], bh[2], bh[3]);
            }
            const int colb = j * 8 + 2 * (lane & 3);
            float p0 = (colb     < limit) ? __expf(sa[0]) : 0.0f;
            float p1 = (colb + 1 < limit) ? __expf(sa[1]) : 0.0f;
            float p2 = (colb     < limit) ? __expf(sa[2]) : 0.0f;
            float p3 = (colb + 1 < limit) ? __expf(sa[3]) : 0.0f;
            lsum0 += p0 + p1;
            lsum1 += p2 + p3;
            const int kk = j >> 1, ro = (j & 1) * 2;
            pah[kk][ro]     = pack2(p0, p1);
            pah[kk][ro + 1] = pack2(p2, p3);
        }

        // ---- GEMM2 (1-term fp16: P @ V), K-dim = 64 keys = 4 k-steps ----
        #pragma unroll
        for (int j2 = 0; j2 < 16; ++j2) {
            #pragma unroll
            for (int kp = 0; kp < 2; ++kp) {
                uint32_t addr = sb + SVT + (j2 * 8 + (lane & 7)) * VROW
                              + (kp * 32 + (lane >> 3) * 8) * 2;
                uint32_t vh[4];
                ldsm4(vh, addr);
                mma16816(o[j2], pah[kp * 2],     vh[0], vh[1]);
                mma16816(o[j2], pah[kp * 2 + 1], vh[2], vh[3]);
            }
        }
    }

    // ---- Epilogue ----
    lsum0 += __shfl_xor_sync(0xffffffffu, lsum0, 1);
    lsum0 += __shfl_xor_sync(0xffffffffu, lsum0, 2);
    lsum1 += __shfl_xor_sync(0xffffffffu, lsum1, 1);
    lsum1 += __shfl_xor_sync(0xffffffffu, lsum1, 2);
    const float inv0 = 1.0f / lsum0;
    const float inv1 = 1.0f / lsum1;

    const int rowA = q0 + warp * 16 + (lane >> 2);
    float* OA = O + ((size_t)b * NQ + rowA) * DVAL + 2 * (lane & 3);
    float* OB = OA + 8 * DVAL;
    #pragma unroll
    for (int j2 = 0; j2 < 16; ++j2) {
        float2 a = make_float2(o[j2][0] * inv0, o[j2][1] * inv0);
        float2 c = make_float2(o[j2][2] * inv1, o[j2][3] * inv1);
        *(float2*)(OA + j2 * 8) = a;
        *(float2*)(OB + j2 * 8) = c;
    }
}

extern "C" void kernel_launch(void* const* d_in, const int* in_sizes, int n_in,
                              void* d_out, int out_size)
{
    (void)in_sizes; (void)n_in; (void)out_size;
    const float* Q  = (const float*)d_in[0];
    const float* K  = (const float*)d_in[1];
    const float* V  = (const float*)d_in[2];
    const int*   VL = (const int*)  d_in[3];
    float* O = (float*)d_out;

    static int configured = 0;
    if (!configured) {
        cudaFuncSetAttribute(fa_mma_kernel,
                             cudaFuncAttributeMaxDynamicSharedMemorySize, SM_TOTAL);
        configured = 1;
    }

    kconv_kernel<<<BATCH * NK * DIM / 4 / 256, 256>>>(K);
    dim3 tg(NK / 32, DVAL / 32, BATCH);
    vtconv_kernel<<<tg, dim3(32, 8)>>>(V);

    dim3 grid(NQ / BM, BATCH);   // q-tile-fast (champion config)
    fa_mma_kernel<<<grid, NTHREADS, SM_TOTAL>>>(Q, VL, O);
}